// round 2
// baseline (speedup 1.0000x reference)
#include <cuda_runtime.h>

// Problem constants
#define B_  8
#define C_  256
#define P_  1024
#define T_  16
#define H_  8
#define D_  32
#define DT  512      // D*T  (contraction dim for energy)
#define PT  16384    // P*T  (token count per batch)
#define BH  64       // B*H

// Scratch (device globals: allocation-free rule)
__device__ float g_K[(size_t)BH * P_ * DT];   // [bh][p][dt]   128 MB
__device__ float g_Q[(size_t)BH * P_ * DT];   // [bh][p][dt]   128 MB
__device__ float g_V[(size_t)BH * DT * P_];   // [bh][dt][p]   128 MB
__device__ float g_E[(size_t)BH * P_ * P_];   // [bh][p][q]    256 MB

#define SPAD 36   // smem row stride (32 + 4 pad)

__device__ __forceinline__ unsigned f2tf(float f) {
    unsigned u;
    asm("cvt.rna.tf32.f32 %0, %1;" : "=r"(u) : "f"(f));
    return u;
}

__device__ __forceinline__ void mma8(float* c, unsigned a0, unsigned a1, unsigned a2, unsigned a3,
                                     unsigned b0, unsigned b1) {
    asm volatile(
        "mma.sync.aligned.m16n8k8.row.col.f32.tf32.tf32.f32 "
        "{%0,%1,%2,%3},{%4,%5,%6,%7},{%8,%9},{%0,%1,%2,%3};"
        : "+f"(c[0]), "+f"(c[1]), "+f"(c[2]), "+f"(c[3])
        : "r"(a0), "r"(a1), "r"(a2), "r"(a3), "r"(b0), "r"(b1));
}

// Core 64x64x32 block-tile compute: 4 warps (2x2), warp tile 32x32.
// A-frag rows = m, B-frag rows = n, both indexed [row][k] in smem.
__device__ __forceinline__ void mma_tile(const unsigned As[64][SPAD], const unsigned Bs[64][SPAD],
                                         float acc[2][4][4], int wm, int wn, int g, int tig) {
#pragma unroll
    for (int kk = 0; kk < 4; kk++) {
        int k8 = kk * 8;
        unsigned a[2][4];
#pragma unroll
        for (int mi = 0; mi < 2; mi++) {
            int r = wm * 32 + mi * 16 + g;
            a[mi][0] = As[r][k8 + tig];
            a[mi][1] = As[r + 8][k8 + tig];
            a[mi][2] = As[r][k8 + tig + 4];
            a[mi][3] = As[r + 8][k8 + tig + 4];
        }
#pragma unroll
        for (int ni = 0; ni < 4; ni++) {
            int r = wn * 32 + ni * 8 + g;
            unsigned b0 = Bs[r][k8 + tig];
            unsigned b1 = Bs[r][k8 + tig + 4];
#pragma unroll
            for (int mi = 0; mi < 2; mi++)
                mma8(acc[mi][ni], a[mi][0], a[mi][1], a[mi][2], a[mi][3], b0, b1);
        }
    }
}

// ---------------------------------------------------------------------------
// Kernel 1: fused K/Q/V projection.  Per (b, which):
//   Y[o, pt] = sum_c W[o,c] * x[b,c,pt]        M=256, N=16384, K=256
// K,Q stored [bh][p][d*16+t];  V stored [bh][d*16+t][p].
// ---------------------------------------------------------------------------
__global__ __launch_bounds__(128) void proj_kernel(const float* __restrict__ x,
                                                   const float* __restrict__ Wk,
                                                   const float* __restrict__ Wq,
                                                   const float* __restrict__ Wv) {
    __shared__ unsigned As[64][SPAD], Bs[64][SPAD];
    int tid = threadIdx.x;
    int lane = tid & 31, warp = tid >> 5;
    int g = lane >> 2, tig = lane & 3;
    int wm = warp >> 1, wn = warp & 1;

    int bz = blockIdx.z;
    int w = bz % 3, b = bz / 3;
    const float* W = (w == 0) ? Wk : (w == 1) ? Wq : Wv;
    int o0 = blockIdx.y * 64;
    int n0 = blockIdx.x * 64;
    const float* xb = x + (size_t)b * C_ * PT;

    float acc[2][4][4];
#pragma unroll
    for (int mi = 0; mi < 2; mi++)
#pragma unroll
        for (int ni = 0; ni < 4; ni++)
#pragma unroll
            for (int e = 0; e < 4; e++) acc[mi][ni][e] = 0.f;

    for (int k0 = 0; k0 < C_; k0 += 32) {
        // A = W tile [64 o][32 c], direct
#pragma unroll
        for (int i = 0; i < 4; i++) {
            int l = tid + i * 128;            // 0..511 float4s
            int row = l >> 3, c4 = l & 7;
            float4 v = *(const float4*)(W + (size_t)(o0 + row) * C_ + k0 + c4 * 4);
            As[row][c4 * 4 + 0] = f2tf(v.x);
            As[row][c4 * 4 + 1] = f2tf(v.y);
            As[row][c4 * 4 + 2] = f2tf(v.z);
            As[row][c4 * 4 + 3] = f2tf(v.w);
        }
        // B = x tile, transposed into [pt][c]
#pragma unroll
        for (int i = 0; i < 4; i++) {
            int l = tid + i * 128;
            int rc = l >> 4, p4 = l & 15;     // rc: c-local 0..31, p4: pt/4 0..15
            float4 v = *(const float4*)(xb + (size_t)(k0 + rc) * PT + n0 + p4 * 4);
            Bs[p4 * 4 + 0][rc] = f2tf(v.x);
            Bs[p4 * 4 + 1][rc] = f2tf(v.y);
            Bs[p4 * 4 + 2][rc] = f2tf(v.z);
            Bs[p4 * 4 + 3][rc] = f2tf(v.w);
        }
        __syncthreads();
        mma_tile(As, Bs, acc, wm, wn, g, tig);
        __syncthreads();
    }

#pragma unroll
    for (int mi = 0; mi < 2; mi++)
#pragma unroll
        for (int ni = 0; ni < 4; ni++)
#pragma unroll
            for (int e = 0; e < 4; e++) {
                int o = o0 + wm * 32 + mi * 16 + g + ((e >= 2) ? 8 : 0);
                int col = n0 + wn * 32 + ni * 8 + 2 * tig + (e & 1);
                int h = o >> 5, d = o & 31;
                int p = col >> 4, t = col & 15;
                size_t bh = (size_t)(b * 8 + h);
                float val = acc[mi][ni][e];
                if (w == 0)
                    g_K[(bh * P_ + p) * DT + d * 16 + t] = val;
                else if (w == 1)
                    g_Q[(bh * P_ + p) * DT + d * 16 + t] = val;
                else
                    g_V[(bh * DT + d * 16 + t) * P_ + p] = val;
            }
}

// ---------------------------------------------------------------------------
// Kernel 2: energy[bh][p][q] = sum_dt K[bh][p][dt] * Q[bh][q][dt]
//   Per bh: M=1024, N=1024, K=512 (pure NT, no transposes)
// ---------------------------------------------------------------------------
__global__ __launch_bounds__(128) void energy_kernel() {
    __shared__ unsigned As[64][SPAD], Bs[64][SPAD];
    int tid = threadIdx.x;
    int lane = tid & 31, warp = tid >> 5;
    int g = lane >> 2, tig = lane & 3;
    int wm = warp >> 1, wn = warp & 1;

    int bh = blockIdx.z;
    int m0 = blockIdx.y * 64;   // p
    int n0 = blockIdx.x * 64;   // q
    const float* Kp = g_K + (size_t)bh * P_ * DT;
    const float* Qp = g_Q + (size_t)bh * P_ * DT;

    float acc[2][4][4];
#pragma unroll
    for (int mi = 0; mi < 2; mi++)
#pragma unroll
        for (int ni = 0; ni < 4; ni++)
#pragma unroll
            for (int e = 0; e < 4; e++) acc[mi][ni][e] = 0.f;

    for (int k0 = 0; k0 < DT; k0 += 32) {
#pragma unroll
        for (int i = 0; i < 4; i++) {
            int l = tid + i * 128;
            int row = l >> 3, c4 = l & 7;
            float4 v = *(const float4*)(Kp + (size_t)(m0 + row) * DT + k0 + c4 * 4);
            As[row][c4 * 4 + 0] = f2tf(v.x);
            As[row][c4 * 4 + 1] = f2tf(v.y);
            As[row][c4 * 4 + 2] = f2tf(v.z);
            As[row][c4 * 4 + 3] = f2tf(v.w);
            float4 u = *(const float4*)(Qp + (size_t)(n0 + row) * DT + k0 + c4 * 4);
            Bs[row][c4 * 4 + 0] = f2tf(u.x);
            Bs[row][c4 * 4 + 1] = f2tf(u.y);
            Bs[row][c4 * 4 + 2] = f2tf(u.z);
            Bs[row][c4 * 4 + 3] = f2tf(u.w);
        }
        __syncthreads();
        mma_tile(As, Bs, acc, wm, wn, g, tig);
        __syncthreads();
    }

    float* Ep = g_E + (size_t)bh * P_ * P_;
#pragma unroll
    for (int mi = 0; mi < 2; mi++)
#pragma unroll
        for (int ni = 0; ni < 4; ni++)
#pragma unroll
            for (int e = 0; e < 4; e++) {
                int p = m0 + wm * 32 + mi * 16 + g + ((e >= 2) ? 8 : 0);
                int q = n0 + wn * 32 + ni * 8 + 2 * tig + (e & 1);
                Ep[(size_t)p * P_ + q] = acc[mi][ni][e];
            }
}

// ---------------------------------------------------------------------------
// Kernel 3: in-place row softmax of energy/SCALE over q (row length 1024)
// ---------------------------------------------------------------------------
__global__ __launch_bounds__(256) void softmax_kernel() {
    int p = blockIdx.x;
    int bh = blockIdx.y;
    float* row = g_E + ((size_t)bh * P_ + p) * P_;
    int tid = threadIdx.x;
    int lane = tid & 31, warp = tid >> 5;
    const float invs = 0.044194173824159216f;  // 1/sqrt(512)

    float4 v = *(const float4*)(row + tid * 4);
    float lx = v.x * invs, ly = v.y * invs, lz = v.z * invs, lw = v.w * invs;

    __shared__ float sm[8];
    float m = fmaxf(fmaxf(lx, ly), fmaxf(lz, lw));
#pragma unroll
    for (int off = 16; off > 0; off >>= 1) m = fmaxf(m, __shfl_xor_sync(0xffffffffu, m, off));
    if (lane == 0) sm[warp] = m;
    __syncthreads();
    m = sm[0];
#pragma unroll
    for (int i = 1; i < 8; i++) m = fmaxf(m, sm[i]);
    __syncthreads();

    float ex = __expf(lx - m), ey = __expf(ly - m), ez = __expf(lz - m), ew = __expf(lw - m);
    float s = ex + ey + ez + ew;
#pragma unroll
    for (int off = 16; off > 0; off >>= 1) s += __shfl_xor_sync(0xffffffffu, s, off);
    if (lane == 0) sm[warp] = s;
    __syncthreads();
    s = sm[0];
#pragma unroll
    for (int i = 1; i < 8; i++) s += sm[i];
    float inv = 1.0f / s;

    *(float4*)(row + tid * 4) = make_float4(ex * inv, ey * inv, ez * inv, ew * inv);
}

// ---------------------------------------------------------------------------
// Kernel 4: out[bh][q][dt] = sum_p attn[bh][p][q] * V[bh][dt][p]
//   Per bh: M=1024 (q), N=512 (dt), K=1024 (p).  A = attn^T (transposed load),
//   B = V[dt][p] direct.  Epilogue scatters into [B, C, P, T].
// ---------------------------------------------------------------------------
__global__ __launch_bounds__(128) void av_kernel(float* __restrict__ out) {
    __shared__ unsigned As[64][SPAD], Bs[64][SPAD];
    int tid = threadIdx.x;
    int lane = tid & 31, warp = tid >> 5;
    int g = lane >> 2, tig = lane & 3;
    int wm = warp >> 1, wn = warp & 1;

    int bh = blockIdx.z;
    int b = bh >> 3, h = bh & 7;
    int m0 = blockIdx.y * 64;   // q
    int n0 = blockIdx.x * 64;   // dt
    const float* Ap = g_E + (size_t)bh * P_ * P_;   // attn [p][q]
    const float* Vp = g_V + (size_t)bh * DT * P_;   // [dt][p]

    float acc[2][4][4];
#pragma unroll
    for (int mi = 0; mi < 2; mi++)
#pragma unroll
        for (int ni = 0; ni < 4; ni++)
#pragma unroll
            for (int e = 0; e < 4; e++) acc[mi][ni][e] = 0.f;

    for (int k0 = 0; k0 < P_; k0 += 32) {
        // A = attn^T tile: read [p][q], store As[q][p]
#pragma unroll
        for (int i = 0; i < 4; i++) {
            int l = tid + i * 128;
            int rp = l >> 4, q4 = l & 15;
            float4 v = *(const float4*)(Ap + (size_t)(k0 + rp) * P_ + m0 + q4 * 4);
            As[q4 * 4 + 0][rp] = f2tf(v.x);
            As[q4 * 4 + 1][rp] = f2tf(v.y);
            As[q4 * 4 + 2][rp] = f2tf(v.z);
            As[q4 * 4 + 3][rp] = f2tf(v.w);
            // B = V tile [dt][p], direct
            int rj = l >> 3, p4 = l & 7;
            float4 u = *(const float4*)(Vp + (size_t)(n0 + rj) * P_ + k0 + p4 * 4);
            Bs[rj][p4 * 4 + 0] = f2tf(u.x);
            Bs[rj][p4 * 4 + 1] = f2tf(u.y);
            Bs[rj][p4 * 4 + 2] = f2tf(u.z);
            Bs[rj][p4 * 4 + 3] = f2tf(u.w);
        }
        __syncthreads();
        mma_tile(As, Bs, acc, wm, wn, g, tig);
        __syncthreads();
    }

#pragma unroll
    for (int mi = 0; mi < 2; mi++)
#pragma unroll
        for (int ni = 0; ni < 4; ni++)
#pragma unroll
            for (int e = 0; e < 4; e++) {
                int q = m0 + wm * 32 + mi * 16 + g + ((e >= 2) ? 8 : 0);
                int j = n0 + wn * 32 + ni * 8 + 2 * tig + (e & 1);
                int d = j >> 4, t = j & 15;
                out[(((size_t)b * C_ + h * D_ + d) * P_ + q) * T_ + t] = acc[mi][ni][e];
            }
}

// ---------------------------------------------------------------------------
extern "C" void kernel_launch(void* const* d_in, const int* in_sizes, int n_in,
                              void* d_out, int out_size) {
    const float* x  = (const float*)d_in[0];
    const float* Wk = (const float*)d_in[1];
    const float* Wq = (const float*)d_in[2];
    const float* Wv = (const float*)d_in[3];
    float* out = (float*)d_out;

    proj_kernel<<<dim3(PT / 64, C_ / 64, 3 * B_), 128>>>(x, Wk, Wq, Wv);
    energy_kernel<<<dim3(P_ / 64, P_ / 64, BH), 128>>>();
    softmax_kernel<<<dim3(P_, BH), 256>>>();
    av_kernel<<<dim3(DT / 64, P_ / 64, BH), 128>>>(out);
}

// round 3
// speedup vs baseline: 1.8220x; 1.8220x over previous
#include <cuda_runtime.h>

#define B_  8
#define C_  256
#define P_  1024
#define T_  16
#define DT  512      // D*T
#define PT  16384    // P*T
#define BH  64

// Scratch
__device__ float g_K[(size_t)BH * P_ * DT];   // [bh][p][dt]
__device__ float g_Q[(size_t)BH * P_ * DT];   // [bh][p][dt]
__device__ float g_V[(size_t)BH * P_ * DT];   // [bh][p][dt]
__device__ float g_E[(size_t)BH * P_ * P_];   // [bh][p][q]

#define SA 36     // row-k layout row stride ([row][32k] + 4 pad)
#define ST 136    // k-major layout row stride ([32k][128] + 8 pad)
#define NTHR 256

__device__ __forceinline__ unsigned f2tf(float f) {
    unsigned u; asm("cvt.rna.tf32.f32 %0, %1;" : "=r"(u) : "f"(f)); return u;
}
__device__ __forceinline__ void mma8(float* c, unsigned a0, unsigned a1, unsigned a2, unsigned a3,
                                     unsigned b0, unsigned b1) {
    asm volatile(
        "mma.sync.aligned.m16n8k8.row.col.f32.tf32.tf32.f32 "
        "{%0,%1,%2,%3},{%4,%5,%6,%7},{%8,%9},{%0,%1,%2,%3};"
        : "+f"(c[0]), "+f"(c[1]), "+f"(c[2]), "+f"(c[3])
        : "r"(a0), "r"(a1), "r"(a2), "r"(a3), "r"(b0), "r"(b1));
}
__device__ __forceinline__ void cp16(float* s, const float* g) {
    unsigned a = (unsigned)__cvta_generic_to_shared(s);
    asm volatile("cp.async.cg.shared.global [%0], [%1], 16;" :: "r"(a), "l"(g));
}
__device__ __forceinline__ void cpc()  { asm volatile("cp.async.commit_group;"); }
__device__ __forceinline__ void cpw1() { asm volatile("cp.async.wait_group 1;"); }

// ---- tile loaders (cp.async, 16B chunks, tile origin pre-offset) ----
// row-k tile: 128 rows x 32 k (rows stride ldg in gmem)
__device__ __forceinline__ void load_rk(float* buf, const float* g, int ldg, int tid) {
#pragma unroll
    for (int j = 0; j < 4; j++) {
        int c = tid + j * NTHR;
        int row = c >> 3, col = (c & 7) * 4;
        cp16(buf + row * SA + col, g + (size_t)row * ldg + col);
    }
}
// k-major tile: 32 k-rows x 128 cols (rows stride ldg in gmem)
__device__ __forceinline__ void load_t(float* buf, const float* g, int ldg, int tid) {
#pragma unroll
    for (int j = 0; j < 4; j++) {
        int c = tid + j * NTHR;
        int row = c >> 5, col = (c & 31) * 4;
        cp16(buf + row * ST + col, g + (size_t)row * ldg + col);
    }
}

// ---- warp-tile compute (64m x 32n per warp, Ktile=32), tf32 cvt at LDS ----
// A row-k [m][k], B row-k [n][k]
__device__ __forceinline__ void comp_rk_rk(const float* As, const float* Bs, float acc[4][4][4],
                                           int wm, int wn, int g, int tig) {
#pragma unroll
    for (int kk = 0; kk < 4; kk++) {
        int k0 = kk * 8 + tig;
        unsigned a[4][4];
#pragma unroll
        for (int mi = 0; mi < 4; mi++) {
            int r = wm * 64 + mi * 16 + g;
            a[mi][0] = f2tf(As[r * SA + k0]);       a[mi][1] = f2tf(As[(r + 8) * SA + k0]);
            a[mi][2] = f2tf(As[r * SA + k0 + 4]);   a[mi][3] = f2tf(As[(r + 8) * SA + k0 + 4]);
        }
#pragma unroll
        for (int ni = 0; ni < 4; ni++) {
            int r = wn * 32 + ni * 8 + g;
            unsigned b0 = f2tf(Bs[r * SA + k0]), b1 = f2tf(Bs[r * SA + k0 + 4]);
#pragma unroll
            for (int mi = 0; mi < 4; mi++)
                mma8(acc[mi][ni], a[mi][0], a[mi][1], a[mi][2], a[mi][3], b0, b1);
        }
    }
}
// A row-k [m][k], B k-major [k][n]
__device__ __forceinline__ void comp_rk_t(const float* As, const float* Bt, float acc[4][4][4],
                                          int wm, int wn, int g, int tig) {
#pragma unroll
    for (int kk = 0; kk < 4; kk++) {
        int k0 = kk * 8 + tig;
        unsigned a[4][4];
#pragma unroll
        for (int mi = 0; mi < 4; mi++) {
            int r = wm * 64 + mi * 16 + g;
            a[mi][0] = f2tf(As[r * SA + k0]);       a[mi][1] = f2tf(As[(r + 8) * SA + k0]);
            a[mi][2] = f2tf(As[r * SA + k0 + 4]);   a[mi][3] = f2tf(As[(r + 8) * SA + k0 + 4]);
        }
#pragma unroll
        for (int ni = 0; ni < 4; ni++) {
            int n = wn * 32 + ni * 8 + g;
            unsigned b0 = f2tf(Bt[k0 * ST + n]), b1 = f2tf(Bt[(k0 + 4) * ST + n]);
#pragma unroll
            for (int mi = 0; mi < 4; mi++)
                mma8(acc[mi][ni], a[mi][0], a[mi][1], a[mi][2], a[mi][3], b0, b1);
        }
    }
}
// A k-major [k][m], B k-major [k][n]
__device__ __forceinline__ void comp_t_t(const float* At, const float* Bt, float acc[4][4][4],
                                         int wm, int wn, int g, int tig) {
#pragma unroll
    for (int kk = 0; kk < 4; kk++) {
        int k0 = kk * 8 + tig;
        unsigned a[4][4];
#pragma unroll
        for (int mi = 0; mi < 4; mi++) {
            int r = wm * 64 + mi * 16 + g;
            a[mi][0] = f2tf(At[k0 * ST + r]);       a[mi][1] = f2tf(At[k0 * ST + r + 8]);
            a[mi][2] = f2tf(At[(k0 + 4) * ST + r]); a[mi][3] = f2tf(At[(k0 + 4) * ST + r + 8]);
        }
#pragma unroll
        for (int ni = 0; ni < 4; ni++) {
            int n = wn * 32 + ni * 8 + g;
            unsigned b0 = f2tf(Bt[k0 * ST + n]), b1 = f2tf(Bt[(k0 + 4) * ST + n]);
#pragma unroll
            for (int mi = 0; mi < 4; mi++)
                mma8(acc[mi][ni], a[mi][0], a[mi][1], a[mi][2], a[mi][3], b0, b1);
        }
    }
}

#define ZERO_ACC(acc) \
    _Pragma("unroll") for (int mi = 0; mi < 4; mi++) \
    _Pragma("unroll") for (int ni = 0; ni < 4; ni++) \
    _Pragma("unroll") for (int e = 0; e < 4; e++) acc[mi][ni][e] = 0.f;

// ---------------------------------------------------------------------------
// proj: Y[o, pt] = sum_c W[o,c] x[b,c,pt]; K/Q/V all stored [bh][p][dt].
// A = W (row-k, ldg=256), B = x (k-major, ldg=PT). Tile 128m x 128n x 32k.
// ---------------------------------------------------------------------------
__global__ __launch_bounds__(256) void proj_kernel(const float* __restrict__ x,
                                                   const float* __restrict__ Wk,
                                                   const float* __restrict__ Wq,
                                                   const float* __restrict__ Wv) {
    extern __shared__ float sm[];
    const int STG = 4608 + 4352;   // rk tile + t tile
    int tid = threadIdx.x, lane = tid & 31, warp = tid >> 5;
    int g = lane >> 2, tig = lane & 3, wm = warp >> 2, wn = warp & 3;
    int bz = blockIdx.z, w = bz % 3, b = bz / 3;
    const float* W = (w == 0) ? Wk : (w == 1) ? Wq : Wv;
    int m0 = blockIdx.y * 128, n0 = blockIdx.x * 128;
    const float* Ap = W + (size_t)m0 * C_;
    const float* Bp = x + (size_t)b * C_ * PT + n0;

    float acc[4][4][4]; ZERO_ACC(acc);
    const int NIT = C_ / 32;   // 8
    load_rk(sm, Ap, C_, tid);            load_t(sm + 4608, Bp, PT, tid);            cpc();
    load_rk(sm + STG, Ap + 32, C_, tid); load_t(sm + STG + 4608, Bp + 32 * PT, PT, tid); cpc();
    int sc = 0, sl = 2;
    for (int i = 0; i < NIT; i++) {
        cpw1(); __syncthreads();
        if (i + 2 < NIT) {
            load_rk(sm + sl * STG, Ap + (i + 2) * 32, C_, tid);
            load_t(sm + sl * STG + 4608, Bp + (size_t)(i + 2) * 32 * PT, PT, tid);
        }
        cpc();
        comp_rk_t(sm + sc * STG, sm + sc * STG + 4608, acc, wm, wn, g, tig);
        sc = (sc == 2) ? 0 : sc + 1; sl = (sl == 2) ? 0 : sl + 1;
    }

    float* dst = (w == 0) ? g_K : (w == 1) ? g_Q : g_V;
#pragma unroll
    for (int mi = 0; mi < 4; mi++) {
#pragma unroll
        for (int half = 0; half < 2; half++) {
            int o = m0 + wm * 64 + mi * 16 + g + half * 8;
            int h = o >> 5, d = o & 31;
            size_t base = ((size_t)(b * 8 + h)) * P_;
#pragma unroll
            for (int ni = 0; ni < 4; ni++) {
                int col = n0 + wn * 32 + ni * 8 + 2 * tig;
                int p = col >> 4, t = col & 15;
                float2 v = make_float2(acc[mi][ni][2 * half], acc[mi][ni][2 * half + 1]);
                *(float2*)(dst + (base + p) * DT + d * 16 + t) = v;
            }
        }
    }
}

// ---------------------------------------------------------------------------
// energy[bh][p][q] = sum_dt K[p][dt] Q[q][dt].  Both row-k, ldg=512.
// ---------------------------------------------------------------------------
__global__ __launch_bounds__(256) void energy_kernel() {
    extern __shared__ float sm[];
    const int STG = 9216;
    int tid = threadIdx.x, lane = tid & 31, warp = tid >> 5;
    int g = lane >> 2, tig = lane & 3, wm = warp >> 2, wn = warp & 3;
    int bh = blockIdx.z, m0 = blockIdx.y * 128, n0 = blockIdx.x * 128;
    const float* Ap = g_K + (size_t)bh * P_ * DT + (size_t)m0 * DT;
    const float* Bp = g_Q + (size_t)bh * P_ * DT + (size_t)n0 * DT;

    float acc[4][4][4]; ZERO_ACC(acc);
    const int NIT = DT / 32;   // 16
    load_rk(sm, Ap, DT, tid);             load_rk(sm + 4608, Bp, DT, tid);             cpc();
    load_rk(sm + STG, Ap + 32, DT, tid);  load_rk(sm + STG + 4608, Bp + 32, DT, tid);  cpc();
    int sc = 0, sl = 2;
    for (int i = 0; i < NIT; i++) {
        cpw1(); __syncthreads();
        if (i + 2 < NIT) {
            load_rk(sm + sl * STG, Ap + (i + 2) * 32, DT, tid);
            load_rk(sm + sl * STG + 4608, Bp + (i + 2) * 32, DT, tid);
        }
        cpc();
        comp_rk_rk(sm + sc * STG, sm + sc * STG + 4608, acc, wm, wn, g, tig);
        sc = (sc == 2) ? 0 : sc + 1; sl = (sl == 2) ? 0 : sl + 1;
    }

    float* Ep = g_E + (size_t)bh * P_ * P_;
#pragma unroll
    for (int mi = 0; mi < 4; mi++) {
        int p = m0 + wm * 64 + mi * 16 + g;
#pragma unroll
        for (int ni = 0; ni < 4; ni++) {
            int q = n0 + wn * 32 + ni * 8 + 2 * tig;
            *(float2*)(Ep + (size_t)p * P_ + q)       = make_float2(acc[mi][ni][0], acc[mi][ni][1]);
            *(float2*)(Ep + (size_t)(p + 8) * P_ + q) = make_float2(acc[mi][ni][2], acc[mi][ni][3]);
        }
    }
}

// ---------------------------------------------------------------------------
// softmax rows of E / sqrt(512), in place
// ---------------------------------------------------------------------------
__global__ __launch_bounds__(256) void softmax_kernel() {
    int p = blockIdx.x, bh = blockIdx.y;
    float* row = g_E + ((size_t)bh * P_ + p) * P_;
    int tid = threadIdx.x, lane = tid & 31, warp = tid >> 5;
    const float invs = 0.044194173824159216f;  // 1/sqrt(512)

    float4 v = *(const float4*)(row + tid * 4);
    float lx = v.x * invs, ly = v.y * invs, lz = v.z * invs, lw = v.w * invs;

    __shared__ float smx[8];
    float m = fmaxf(fmaxf(lx, ly), fmaxf(lz, lw));
#pragma unroll
    for (int off = 16; off > 0; off >>= 1) m = fmaxf(m, __shfl_xor_sync(0xffffffffu, m, off));
    if (lane == 0) smx[warp] = m;
    __syncthreads();
    m = smx[0];
#pragma unroll
    for (int i = 1; i < 8; i++) m = fmaxf(m, smx[i]);
    __syncthreads();

    float ex = __expf(lx - m), ey = __expf(ly - m), ez = __expf(lz - m), ew = __expf(lw - m);
    float s = ex + ey + ez + ew;
#pragma unroll
    for (int off = 16; off > 0; off >>= 1) s += __shfl_xor_sync(0xffffffffu, s, off);
    if (lane == 0) smx[warp] = s;
    __syncthreads();
    s = smx[0];
#pragma unroll
    for (int i = 1; i < 8; i++) s += smx[i];
    float inv = 1.0f / s;
    *(float4*)(row + tid * 4) = make_float4(ex * inv, ey * inv, ez * inv, ew * inv);
}

// ---------------------------------------------------------------------------
// av: out[q][dt] = sum_p attn[p][q] V[p][dt].  Both operands k-major (k=p).
//   A from E [p][q] (ldg=1024), B from V [p][dt] (ldg=512).
// ---------------------------------------------------------------------------
__global__ __launch_bounds__(256) void av_kernel(float* __restrict__ out) {
    extern __shared__ float sm[];
    const int STG = 8704;   // two t tiles
    int tid = threadIdx.x, lane = tid & 31, warp = tid >> 5;
    int g = lane >> 2, tig = lane & 3, wm = warp >> 2, wn = warp & 3;
    int bh = blockIdx.z, b = bh >> 3, h = bh & 7;
    int m0 = blockIdx.y * 128;   // q
    int n0 = blockIdx.x * 128;   // dt
    const float* Ap = g_E + (size_t)bh * P_ * P_ + m0;     // rows k=p, cols q
    const float* Bp = g_V + (size_t)bh * P_ * DT + n0;     // rows k=p, cols dt

    float acc[4][4][4]; ZERO_ACC(acc);
    const int NIT = P_ / 32;   // 32
    load_t(sm, Ap, P_, tid);                       load_t(sm + 4352, Bp, DT, tid);                       cpc();
    load_t(sm + STG, Ap + 32 * P_, P_, tid);       load_t(sm + STG + 4352, Bp + 32 * DT, DT, tid);       cpc();
    int sc = 0, sl = 2;
    for (int i = 0; i < NIT; i++) {
        cpw1(); __syncthreads();
        if (i + 2 < NIT) {
            load_t(sm + sl * STG, Ap + (size_t)(i + 2) * 32 * P_, P_, tid);
            load_t(sm + sl * STG + 4352, Bp + (size_t)(i + 2) * 32 * DT, DT, tid);
        }
        cpc();
        comp_t_t(sm + sc * STG, sm + sc * STG + 4352, acc, wm, wn, g, tig);
        sc = (sc == 2) ? 0 : sc + 1; sl = (sl == 2) ? 0 : sl + 1;
    }

#pragma unroll
    for (int mi = 0; mi < 4; mi++) {
#pragma unroll
        for (int half = 0; half < 2; half++) {
            int q = m0 + wm * 64 + mi * 16 + g + half * 8;
#pragma unroll
            for (int ni = 0; ni < 4; ni++) {
                int n = n0 + wn * 32 + ni * 8 + 2 * tig;
                int d = n >> 4, t = n & 15;
                float2 v = make_float2(acc[mi][ni][2 * half], acc[mi][ni][2 * half + 1]);
                *(float2*)(out + (((size_t)b * C_ + h * 32 + d) * P_ + q) * T_ + t) = v;
            }
        }
    }
}

// ---------------------------------------------------------------------------
extern "C" void kernel_launch(void* const* d_in, const int* in_sizes, int n_in,
                              void* d_out, int out_size) {
    const float* x  = (const float*)d_in[0];
    const float* Wk = (const float*)d_in[1];
    const float* Wq = (const float*)d_in[2];
    const float* Wv = (const float*)d_in[3];
    float* out = (float*)d_out;

    const int SM_PROJ = 3 * (4608 + 4352) * 4;
    const int SM_EN   = 3 * 9216 * 4;
    const int SM_AV   = 3 * 8704 * 4;
    cudaFuncSetAttribute(proj_kernel,   cudaFuncAttributeMaxDynamicSharedMemorySize, SM_PROJ);
    cudaFuncSetAttribute(energy_kernel, cudaFuncAttributeMaxDynamicSharedMemorySize, SM_EN);
    cudaFuncSetAttribute(av_kernel,     cudaFuncAttributeMaxDynamicSharedMemorySize, SM_AV);

    proj_kernel<<<dim3(PT / 128, C_ / 128, 3 * B_), 256, SM_PROJ>>>(x, Wk, Wq, Wv);
    energy_kernel<<<dim3(P_ / 128, P_ / 128, BH), 256, SM_EN>>>();
    softmax_kernel<<<dim3(P_, BH), 256>>>();
    av_kernel<<<dim3(DT / 128, P_ / 128, BH), 256, SM_AV>>>(out);
}

// round 4
// speedup vs baseline: 1.8634x; 1.0228x over previous
#include <cuda_runtime.h>

#define B_  8
#define C_  256
#define P_  1024
#define T_  16
#define DT  512      // D*T
#define PT  16384    // P*T
#define BH  64

// Scratch.  K,Q stored with dt pair-permuted; V plain; E stored with q pair-permuted.
__device__ float g_K[(size_t)BH * P_ * DT];   // [bh][p][perm(dt)]
__device__ float g_Q[(size_t)BH * P_ * DT];   // [bh][p][perm(dt)]
__device__ float g_V[(size_t)BH * P_ * DT];   // [bh][p][dt]
__device__ float g_E[(size_t)BH * P_ * P_];   // [bh][p][permq(q)]

#define SA 36     // proj row-k stride
#define ST 136    // k-major stride ([32k][128] + 8 pad)
#define SE 40     // energy row-k stride (conflict-free for LDS.64 frags)
#define NTHR 256

__device__ __forceinline__ unsigned f2tf(float f) {
    unsigned u; asm("cvt.rna.tf32.f32 %0, %1;" : "=r"(u) : "f"(f)); return u;
}
__device__ __forceinline__ float rtf(float f) { return __uint_as_float(f2tf(f)); }

__device__ __forceinline__ void mma8(float* c, unsigned a0, unsigned a1, unsigned a2, unsigned a3,
                                     unsigned b0, unsigned b1) {
    asm volatile(
        "mma.sync.aligned.m16n8k8.row.col.f32.tf32.tf32.f32 "
        "{%0,%1,%2,%3},{%4,%5,%6,%7},{%8,%9},{%0,%1,%2,%3};"
        : "+f"(c[0]), "+f"(c[1]), "+f"(c[2]), "+f"(c[3])
        : "r"(a0), "r"(a1), "r"(a2), "r"(a3), "r"(b0), "r"(b1));
}
__device__ __forceinline__ void cp16(float* s, const float* g) {
    unsigned a = (unsigned)__cvta_generic_to_shared(s);
    asm volatile("cp.async.cg.shared.global [%0], [%1], 16;" :: "r"(a), "l"(g));
}
__device__ __forceinline__ void cpc()  { asm volatile("cp.async.commit_group;"); }
__device__ __forceinline__ void cpw1() { asm volatile("cp.async.wait_group 1;"); }

// ---- tile loaders ----
// proj: row-k tile 128x32 (stride SA)
__device__ __forceinline__ void load_rk(float* buf, const float* g, int ldg, int tid) {
#pragma unroll
    for (int j = 0; j < 4; j++) {
        int c = tid + j * NTHR;
        int row = c >> 3, col = (c & 7) * 4;
        cp16(buf + row * SA + col, g + (size_t)row * ldg + col);
    }
}
// k-major tile 32x128 (stride ST)
__device__ __forceinline__ void load_t(float* buf, const float* g, int ldg, int tid) {
#pragma unroll
    for (int j = 0; j < 4; j++) {
        int c = tid + j * NTHR;
        int row = c >> 5, col = (c & 31) * 4;
        cp16(buf + row * ST + col, g + (size_t)row * ldg + col);
    }
}
// energy: row-k tile 128x32 (stride SE, ldg = DT)
__device__ __forceinline__ void load_e(float* buf, const float* g, int tid) {
#pragma unroll
    for (int j = 0; j < 4; j++) {
        int c = tid + j * NTHR;
        int row = c >> 3, col = (c & 7) * 4;
        cp16(buf + row * SE + col, g + (size_t)row * DT + col);
    }
}

// ---- proj compute: A row-k [m][k] (cvt), B k-major [k][n] (cvt) ----
__device__ __forceinline__ void comp_rk_t(const float* As, const float* Bt, float acc[4][4][4],
                                          int wm, int wn, int g, int tig) {
#pragma unroll
    for (int kk = 0; kk < 4; kk++) {
        int k0 = kk * 8 + tig;
        unsigned a[4][4];
#pragma unroll
        for (int mi = 0; mi < 4; mi++) {
            int r = wm * 64 + mi * 16 + g;
            a[mi][0] = f2tf(As[r * SA + k0]);       a[mi][1] = f2tf(As[(r + 8) * SA + k0]);
            a[mi][2] = f2tf(As[r * SA + k0 + 4]);   a[mi][3] = f2tf(As[(r + 8) * SA + k0 + 4]);
        }
#pragma unroll
        for (int ni = 0; ni < 4; ni++) {
            int n = wn * 32 + ni * 8 + g;
            unsigned b0 = f2tf(Bt[k0 * ST + n]), b1 = f2tf(Bt[(k0 + 4) * ST + n]);
#pragma unroll
            for (int mi = 0; mi < 4; mi++)
                mma8(acc[mi][ni], a[mi][0], a[mi][1], a[mi][2], a[mi][3], b0, b1);
        }
    }
}

// ---- energy compute: both row-k, k pair-permuted -> float2 frags, no cvt ----
__device__ __forceinline__ void comp_e(const float* As, const float* Bs, float acc[4][4][4],
                                       int wm, int wn, int g, int tig) {
#pragma unroll
    for (int kk = 0; kk < 4; kk++) {
        int kc = kk * 8 + 2 * tig;
        unsigned a[4][4];
#pragma unroll
        for (int mi = 0; mi < 4; mi++) {
            int r = wm * 64 + mi * 16 + g;
            float2 lo = *(const float2*)(As + r * SE + kc);
            float2 hi = *(const float2*)(As + (r + 8) * SE + kc);
            a[mi][0] = __float_as_uint(lo.x); a[mi][1] = __float_as_uint(hi.x);
            a[mi][2] = __float_as_uint(lo.y); a[mi][3] = __float_as_uint(hi.y);
        }
#pragma unroll
        for (int ni = 0; ni < 4; ni++) {
            int rn = wn * 32 + ni * 8 + g;
            float2 vb = *(const float2*)(Bs + rn * SE + kc);
            unsigned b0 = __float_as_uint(vb.x), b1 = __float_as_uint(vb.y);
#pragma unroll
            for (int mi = 0; mi < 4; mi++)
                mma8(acc[mi][ni], a[mi][0], a[mi][1], a[mi][2], a[mi][3], b0, b1);
        }
    }
}

// ---- av compute: A k-major with m pair-permuted cols -> float2 frags; B k-major scalar ----
__device__ __forceinline__ void comp_av(const float* At, const float* Bt, float acc[4][4][4],
                                        int wm, int wn, int g, int tig) {
#pragma unroll
    for (int kk = 0; kk < 4; kk++) {
        int k0 = kk * 8 + tig;
        unsigned a[4][4];
#pragma unroll
        for (int mi = 0; mi < 4; mi++) {
            int cb = wm * 64 + mi * 16 + 2 * g;
            float2 lo = *(const float2*)(At + k0 * ST + cb);        // (m=g, m=g+8) @ k0
            float2 hi = *(const float2*)(At + (k0 + 4) * ST + cb);  // @ k0+4
            a[mi][0] = __float_as_uint(lo.x); a[mi][1] = __float_as_uint(lo.y);
            a[mi][2] = __float_as_uint(hi.x); a[mi][3] = __float_as_uint(hi.y);
        }
#pragma unroll
        for (int ni = 0; ni < 4; ni++) {
            int n = wn * 32 + ni * 8 + g;
            unsigned b0 = __float_as_uint(Bt[k0 * ST + n]);
            unsigned b1 = __float_as_uint(Bt[(k0 + 4) * ST + n]);
#pragma unroll
            for (int mi = 0; mi < 4; mi++)
                mma8(acc[mi][ni], a[mi][0], a[mi][1], a[mi][2], a[mi][3], b0, b1);
        }
    }
}

#define ZERO_ACC(acc) \
    _Pragma("unroll") for (int mi = 0; mi < 4; mi++) \
    _Pragma("unroll") for (int ni = 0; ni < 4; ni++) \
    _Pragma("unroll") for (int e = 0; e < 4; e++) acc[mi][ni][e] = 0.f;

// ---------------------------------------------------------------------------
// proj: Y[o, pt] = sum_c W[o,c] x[b,c,pt]
// K,Q: [bh][p][perm8(dt)] rounded;  V: [bh][p][dt] rounded.
// ---------------------------------------------------------------------------
__global__ __launch_bounds__(256) void proj_kernel(const float* __restrict__ x,
                                                   const float* __restrict__ Wk,
                                                   const float* __restrict__ Wq,
                                                   const float* __restrict__ Wv) {
    extern __shared__ float sm[];
    const int STG = 4608 + 4352;
    int tid = threadIdx.x, lane = tid & 31, warp = tid >> 5;
    int g = lane >> 2, tig = lane & 3, wm = warp >> 2, wn = warp & 3;
    int bz = blockIdx.z, w = bz % 3, b = bz / 3;
    const float* W = (w == 0) ? Wk : (w == 1) ? Wq : Wv;
    int m0 = blockIdx.y * 128, n0 = blockIdx.x * 128;
    const float* Ap = W + (size_t)m0 * C_;
    const float* Bp = x + (size_t)b * C_ * PT + n0;

    float acc[4][4][4]; ZERO_ACC(acc);
    const int NIT = C_ / 32;
    load_rk(sm, Ap, C_, tid);            load_t(sm + 4608, Bp, PT, tid);            cpc();
    load_rk(sm + STG, Ap + 32, C_, tid); load_t(sm + STG + 4608, Bp + 32 * PT, PT, tid); cpc();
    int sc = 0, sl = 2;
    for (int i = 0; i < NIT; i++) {
        cpw1(); __syncthreads();
        if (i + 2 < NIT) {
            load_rk(sm + sl * STG, Ap + (i + 2) * 32, C_, tid);
            load_t(sm + sl * STG + 4608, Bp + (size_t)(i + 2) * 32 * PT, PT, tid);
        }
        cpc();
        comp_rk_t(sm + sc * STG, sm + sc * STG + 4608, acc, wm, wn, g, tig);
        sc = (sc == 2) ? 0 : sc + 1; sl = (sl == 2) ? 0 : sl + 1;
    }

    if (w == 2) {
        // V: plain layout, rounded, float2 stores
#pragma unroll
        for (int mi = 0; mi < 4; mi++)
#pragma unroll
            for (int half = 0; half < 2; half++) {
                int o = m0 + wm * 64 + mi * 16 + g + half * 8;
                int h = o >> 5, d = o & 31;
                size_t base = ((size_t)(b * 8 + h)) * P_;
#pragma unroll
                for (int ni = 0; ni < 4; ni++) {
                    int col = n0 + wn * 32 + ni * 8 + 2 * tig;
                    int p = col >> 4, t = col & 15;
                    float2 v = make_float2(rtf(acc[mi][ni][2 * half]), rtf(acc[mi][ni][2 * half + 1]));
                    *(float2*)(g_V + (base + p) * DT + d * 16 + t) = v;
                }
            }
    } else {
        float* dst = (w == 0) ? g_K : g_Q;
#pragma unroll
        for (int mi = 0; mi < 4; mi++)
#pragma unroll
            for (int half = 0; half < 2; half++) {
                int o = m0 + wm * 64 + mi * 16 + g + half * 8;
                int h = o >> 5, d = o & 31;
                size_t base = ((size_t)(b * 8 + h)) * P_;
#pragma unroll
                for (int ni = 0; ni < 4; ni++)
#pragma unroll
                    for (int e = 0; e < 2; e++) {
                        int col = n0 + wn * 32 + ni * 8 + 2 * tig + e;
                        int p = col >> 4, t = col & 15;
                        int tp = (t & 8) | ((t & 3) << 1) | ((t >> 2) & 1);  // pair-perm within 8
                        dst[(base + p) * DT + d * 16 + tp] = rtf(acc[mi][ni][2 * half + e]);
                    }
            }
    }
}

// ---------------------------------------------------------------------------
// energy[bh][p][permq(q)] = sum_dt K[p][dt] Q[q][dt]   (k-permutation cancels)
// 2-stage pipeline, vectorized float2 fragments, no cvt.
// ---------------------------------------------------------------------------
__global__ __launch_bounds__(256) void energy_kernel() {
    extern __shared__ float sm[];
    const int TSZ = 128 * SE;     // 5120
    const int STG = 2 * TSZ;      // 10240
    int tid = threadIdx.x, lane = tid & 31, warp = tid >> 5;
    int g = lane >> 2, tig = lane & 3, wm = warp >> 2, wn = warp & 3;
    int bh = blockIdx.z, m0 = blockIdx.y * 128, n0 = blockIdx.x * 128;
    const float* Ap = g_K + (size_t)bh * P_ * DT + (size_t)m0 * DT;
    const float* Bp = g_Q + (size_t)bh * P_ * DT + (size_t)n0 * DT;

    float acc[4][4][4]; ZERO_ACC(acc);
    const int NIT = DT / 32;   // 16
    load_e(sm, Ap, tid);       load_e(sm + TSZ, Bp, tid);       cpc();
    load_e(sm + STG, Ap + 32, tid); load_e(sm + STG + TSZ, Bp + 32, tid); cpc();
    for (int i = 0; i < NIT; i++) {
        cpw1(); __syncthreads();
        const float* As = sm + (i & 1) * STG;
        comp_e(As, As + TSZ, acc, wm, wn, g, tig);
        __syncthreads();
        if (i + 2 < NIT) {
            load_e(sm + (i & 1) * STG, Ap + (i + 2) * 32, tid);
            load_e(sm + (i & 1) * STG + TSZ, Bp + (i + 2) * 32, tid);
        }
        cpc();
    }

    float* Ep = g_E + (size_t)bh * P_ * P_;
#pragma unroll
    for (int mi = 0; mi < 4; mi++) {
        int p = m0 + wm * 64 + mi * 16 + g;
#pragma unroll
        for (int ni = 0; ni < 4; ni++)
#pragma unroll
            for (int e = 0; e < 4; e++) {
                int q = n0 + wn * 32 + ni * 8 + 2 * tig + (e & 1);
                int qp = (q & ~15) | ((q & 7) << 1) | ((q >> 3) & 1);   // pair-perm within 16
                Ep[(size_t)(p + ((e >= 2) ? 8 : 0)) * P_ + qp] = acc[mi][ni][e];
            }
    }
}

// ---------------------------------------------------------------------------
// softmax rows of E / sqrt(512), in place (permutation-invariant); rounds output
// ---------------------------------------------------------------------------
__global__ __launch_bounds__(256) void softmax_kernel() {
    int p = blockIdx.x, bh = blockIdx.y;
    float* row = g_E + ((size_t)bh * P_ + p) * P_;
    int tid = threadIdx.x, lane = tid & 31, warp = tid >> 5;
    const float invs = 0.044194173824159216f;

    float4 v = *(const float4*)(row + tid * 4);
    float lx = v.x * invs, ly = v.y * invs, lz = v.z * invs, lw = v.w * invs;

    __shared__ float smx[8];
    float m = fmaxf(fmaxf(lx, ly), fmaxf(lz, lw));
#pragma unroll
    for (int off = 16; off > 0; off >>= 1) m = fmaxf(m, __shfl_xor_sync(0xffffffffu, m, off));
    if (lane == 0) smx[warp] = m;
    __syncthreads();
    m = smx[0];
#pragma unroll
    for (int i = 1; i < 8; i++) m = fmaxf(m, smx[i]);
    __syncthreads();

    float ex = __expf(lx - m), ey = __expf(ly - m), ez = __expf(lz - m), ew = __expf(lw - m);
    float s = ex + ey + ez + ew;
#pragma unroll
    for (int off = 16; off > 0; off >>= 1) s += __shfl_xor_sync(0xffffffffu, s, off);
    if (lane == 0) smx[warp] = s;
    __syncthreads();
    s = smx[0];
#pragma unroll
    for (int i = 1; i < 8; i++) s += smx[i];
    float inv = 1.0f / s;
    *(float4*)(row + tid * 4) =
        make_float4(rtf(ex * inv), rtf(ey * inv), rtf(ez * inv), rtf(ew * inv));
}

// ---------------------------------------------------------------------------
// av: out[q][dt] = sum_p attn[p][q] V[p][dt].
// A = E k-major (cols q pair-permuted -> float2 frags), B = V k-major scalar.
// ---------------------------------------------------------------------------
__global__ __launch_bounds__(256) void av_kernel(float* __restrict__ out) {
    extern __shared__ float sm[];
    const int STG = 8704;
    int tid = threadIdx.x, lane = tid & 31, warp = tid >> 5;
    int g = lane >> 2, tig = lane & 3, wm = warp >> 2, wn = warp & 3;
    int bh = blockIdx.z, b = bh >> 3, h = bh & 7;
    int m0 = blockIdx.y * 128;   // q
    int n0 = blockIdx.x * 128;   // dt
    const float* Ap = g_E + (size_t)bh * P_ * P_ + m0;
    const float* Bp = g_V + (size_t)bh * P_ * DT + n0;

    float acc[4][4][4]; ZERO_ACC(acc);
    const int NIT = P_ / 32;   // 32
    load_t(sm, Ap, P_, tid);                 load_t(sm + 4352, Bp, DT, tid);                 cpc();
    load_t(sm + STG, Ap + 32 * P_, P_, tid); load_t(sm + STG + 4352, Bp + 32 * DT, DT, tid); cpc();
    int sc = 0, sl = 2;
    for (int i = 0; i < NIT; i++) {
        cpw1(); __syncthreads();
        if (i + 2 < NIT) {
            load_t(sm + sl * STG, Ap + (size_t)(i + 2) * 32 * P_, P_, tid);
            load_t(sm + sl * STG + 4352, Bp + (size_t)(i + 2) * 32 * DT, DT, tid);
        }
        cpc();
        comp_av(sm + sc * STG, sm + sc * STG + 4352, acc, wm, wn, g, tig);
        sc = (sc == 2) ? 0 : sc + 1; sl = (sl == 2) ? 0 : sl + 1;
    }

#pragma unroll
    for (int mi = 0; mi < 4; mi++)
#pragma unroll
        for (int half = 0; half < 2; half++) {
            int q = m0 + wm * 64 + mi * 16 + g + half * 8;
#pragma unroll
            for (int ni = 0; ni < 4; ni++) {
                int n = n0 + wn * 32 + ni * 8 + 2 * tig;
                int d = n >> 4, t = n & 15;
                float2 v = make_float2(acc[mi][ni][2 * half], acc[mi][ni][2 * half + 1]);
                *(float2*)(out + (((size_t)b * C_ + h * 32 + d) * P_ + q) * T_ + t) = v;
            }
        }
}

// ---------------------------------------------------------------------------
extern "C" void kernel_launch(void* const* d_in, const int* in_sizes, int n_in,
                              void* d_out, int out_size) {
    const float* x  = (const float*)d_in[0];
    const float* Wk = (const float*)d_in[1];
    const float* Wq = (const float*)d_in[2];
    const float* Wv = (const float*)d_in[3];
    float* out = (float*)d_out;

    const int SM_PROJ = 3 * (4608 + 4352) * 4;   // 107520
    const int SM_EN   = 2 * 2 * 128 * SE * 4;    // 81920
    const int SM_AV   = 3 * 8704 * 4;            // 104448
    cudaFuncSetAttribute(proj_kernel,   cudaFuncAttributeMaxDynamicSharedMemorySize, SM_PROJ);
    cudaFuncSetAttribute(energy_kernel, cudaFuncAttributeMaxDynamicSharedMemorySize, SM_EN);
    cudaFuncSetAttribute(av_kernel,     cudaFuncAttributeMaxDynamicSharedMemorySize, SM_AV);

    proj_kernel<<<dim3(PT / 128, C_ / 128, 3 * B_), 256, SM_PROJ>>>(x, Wk, Wq, Wv);
    energy_kernel<<<dim3(P_ / 128, P_ / 128, BH), 256, SM_EN>>>();
    softmax_kernel<<<dim3(P_, BH), 256>>>();
    av_kernel<<<dim3(DT / 128, P_ / 128, BH), 256, SM_AV>>>(out);
}